// round 15
// baseline (speedup 1.0000x reference)
#include <cuda_runtime.h>
#include <cuda_fp16.h>
#include <cstdint>

#define T_TOK 8192
#define DIM   1024
#define FFD   4096
#define NEXP  8

// ---- static device scratch (no allocations) ----
__device__ int    g_count[NEXP];
__device__ int    g_offset[NEXP];
__device__ int    g_tok[NEXP * T_TOK];
__device__ float  g_gate[NEXP * T_TOK];
__device__ __half g_xh[(size_t)T_TOK * DIM];
__device__ __half g_w1h[(size_t)NEXP * FFD * DIM];
__device__ __half g_w2h[(size_t)NEXP * DIM * FFD];
__device__ __half g_hh[(size_t)T_TOK * 2 * FFD];

__device__ __forceinline__ void cpa16(unsigned dst, const void* src) {
    asm volatile("cp.async.cg.shared.global [%0], [%1], 16;" :: "r"(dst), "l"(src) : "memory");
}
__device__ __forceinline__ void ldsm4(unsigned r[4], unsigned addr) {
    asm volatile("ldmatrix.sync.aligned.m8n8.x4.shared.b16 {%0,%1,%2,%3}, [%4];"
                 : "=r"(r[0]), "=r"(r[1]), "=r"(r[2]), "=r"(r[3]) : "r"(addr));
}
__device__ __forceinline__ void mma_f16(float c[4], const unsigned a[4], unsigned b0, unsigned b1) {
    asm volatile(
        "mma.sync.aligned.m16n8k16.row.col.f32.f16.f16.f32 "
        "{%0,%1,%2,%3}, {%4,%5,%6,%7}, {%8,%9}, {%0,%1,%2,%3};"
        : "+f"(c[0]), "+f"(c[1]), "+f"(c[2]), "+f"(c[3])
        : "r"(a[0]), "r"(a[1]), "r"(a[2]), "r"(a[3]), "r"(b0), "r"(b1));
}
__device__ __forceinline__ void red2(float* p, float v0, float v1) {
    asm volatile("red.global.add.v2.f32 [%0], {%1, %2};" :: "l"(p), "f"(v0), "f"(v1) : "memory");
}

// ---- init routing counters ----
__global__ void k_init() {
    if (threadIdx.x < NEXP) g_count[threadIdx.x] = 0;
}

// block ranges inside k_prep
#define NB_W1   16384
#define NB_W2   16384
#define NB_X    4096
#define NB_GATE 1024

__device__ __forceinline__ void cvt8(const float4* in, uint4* out, int i) {
    float4 a = in[2 * i], b = in[2 * i + 1];
    __half2 h0 = __floats2half2_rn(a.x, a.y);
    __half2 h1 = __floats2half2_rn(a.z, a.w);
    __half2 h2 = __floats2half2_rn(b.x, b.y);
    __half2 h3 = __floats2half2_rn(b.z, b.w);
    uint4 v;
    v.x = *reinterpret_cast<unsigned*>(&h0);
    v.y = *reinterpret_cast<unsigned*>(&h1);
    v.z = *reinterpret_cast<unsigned*>(&h2);
    v.w = *reinterpret_cast<unsigned*>(&h3);
    out[i] = v;
}

// ---- fused prep: weight/x fp16 conversion + out zero + gating, one launch ----
__global__ void __launch_bounds__(256)
k_prep(const float* __restrict__ x, const float* __restrict__ wg,
       const float* __restrict__ bg, const float* __restrict__ w1,
       const float* __restrict__ w2, float* __restrict__ out,
       int out_size, int has_tail, int nb_zero) {
    __shared__ float s_wg[NEXP * DIM];
    __shared__ float s_bg[NEXP];
    int b = blockIdx.x, tid = threadIdx.x;

    if (b < NB_W1) {
        cvt8((const float4*)w1, (uint4*)g_w1h, b * 256 + tid);
        return;
    }
    b -= NB_W1;
    if (b < NB_W2) {
        cvt8((const float4*)w2, (uint4*)g_w2h, b * 256 + tid);
        return;
    }
    b -= NB_W2;
    if (b < NB_X) {
        cvt8((const float4*)x, (uint4*)g_xh, b * 256 + tid);
        return;
    }
    b -= NB_X;
    if (b < nb_zero) {
        int i4 = b * 256 + tid;
        int i = i4 * 4;
        if (i < out_size) {
            const int base = T_TOK * DIM;
            if (!(has_tail && i >= base && i < base + 4 * T_TOK))
                *(float4*)(out + i) = make_float4(0.f, 0.f, 0.f, 0.f);
        }
        return;
    }
    b -= nb_zero;

    // ---- gating: one warp per token, 8 tokens per block ----
    for (int i = tid; i < NEXP * DIM; i += 256) s_wg[i] = wg[i];
    if (tid < NEXP) s_bg[tid] = bg[tid];
    __syncthreads();

    int warp = tid >> 5, lane = tid & 31;
    int t = b * 8 + warp;
    const float* xr = x + (size_t)t * DIM;

    float acc[NEXP];
#pragma unroll
    for (int e = 0; e < NEXP; e++) acc[e] = 0.f;
    for (int d = lane; d < DIM; d += 32) {
        float xv = xr[d];
#pragma unroll
        for (int e = 0; e < NEXP; e++) acc[e] += xv * s_wg[e * DIM + d];
    }
#pragma unroll
    for (int e = 0; e < NEXP; e++) {
#pragma unroll
        for (int o = 16; o > 0; o >>= 1) acc[e] += __shfl_xor_sync(0xffffffffu, acc[e], o);
    }

    if (lane == 0) {
        float p[NEXP];
        float m = -1e30f;
#pragma unroll
        for (int e = 0; e < NEXP; e++) { p[e] = acc[e] + s_bg[e]; m = fmaxf(m, p[e]); }
        float s = 0.f;
#pragma unroll
        for (int e = 0; e < NEXP; e++) { p[e] = expf(p[e] - m); s += p[e]; }
        float inv = 1.f / s;
#pragma unroll
        for (int e = 0; e < NEXP; e++) p[e] *= inv;

        int e1 = 0;
#pragma unroll
        for (int e = 1; e < NEXP; e++) if (p[e] > p[e1]) e1 = e;
        int e2 = (e1 == 0) ? 1 : 0;
#pragma unroll
        for (int e = 0; e < NEXP; e++) if (e != e1 && p[e] > p[e2]) e2 = e;

        int pos1 = atomicAdd(&g_count[e1], 1);
        g_tok[e1 * T_TOK + pos1]  = t;
        g_gate[e1 * T_TOK + pos1] = p[e1];
        int pos2 = atomicAdd(&g_count[e2], 1);
        g_tok[e2 * T_TOK + pos2]  = t;
        g_gate[e2 * T_TOK + pos2] = p[e2];

        if (has_tail) {
            float* tail = out + (size_t)T_TOK * DIM;
            tail[t * 2 + 0] = (float)e1;
            tail[t * 2 + 1] = (float)e2;
            tail[T_TOK * 2 + t * 2 + 0] = p[e1];
            tail[T_TOK * 2 + t * 2 + 1] = p[e2];
        }
    }
}

__global__ void k_offsets() {
    int s = 0;
    for (int e = 0; e < NEXP; e++) { g_offset[e] = s; s += g_count[e]; }
}

// ---- fp16 grouped GEMM: 128x128 CTA tile, 4 warps x 64x64 warp tile ----
// BK=64 halfs, 3-stage cp.async (98KB smem), 128 threads, 2 CTAs/SM.
// LDSM:HMMA = 8:32 per k16 per warp (was 6:16) -> L1 traffic x2/3.
// MODE 0: A = gathered g_xh, B = g_w1h -> h = f16(leaky(v + b1))
// MODE 1: A = g_hh,          B = g_w2h -> red.v2(out, (v + b2) * gate)
template <int MODE>
__global__ void __launch_bounds__(128, 2)
k_g(const float* __restrict__ bias, float* __restrict__ out) {
    constexpr int KD = (MODE == 0) ? DIM : FFD;
    constexpr int ND = (MODE == 0) ? FFD : DIM;
    constexpr int KT = KD / 64;

    int e = blockIdx.z;
    int cnt = g_count[e];
    int m0 = blockIdx.y * 128;
    if (m0 >= cnt) return;
    int n0 = blockIdx.x * 128;
    int off = g_offset[e];

    extern __shared__ __align__(1024) char sm[];
    const unsigned sb = (unsigned)__cvta_generic_to_shared(sm);
    int*   s_tok  = (int*)(sm + 98304);
    float* s_gate = (float*)(sm + 98304 + 512);
    float* s_bias = (float*)(sm + 98304 + 1024);

    int tid = threadIdx.x;
    if (tid < 128) {
        int mc = min(m0 + tid, cnt - 1);
        s_tok[tid]  = g_tok[e * T_TOK + mc];
        s_gate[tid] = g_gate[e * T_TOK + mc];
        s_bias[tid] = bias[(size_t)e * ND + n0 + tid];
    }
    __syncthreads();

    const __half* Wb = ((MODE == 0) ? g_w1h : g_w2h) + (size_t)e * ND * KD;

    // loader: 8 threads/row (16B chunk each), rows lr + 16*i, i=0..7
    int lr = tid >> 3, lc = tid & 7;
    const unsigned soff = (unsigned)(lr * 128 + ((lc ^ (lr & 7)) << 4));
    const __half* bBase = Wb + (size_t)(n0 + lr) * KD + lc * 8;

    auto fill = [&](int j) {
        unsigned ab = sb + (unsigned)(j % 3) * 32768u + soff;
        const int k0 = j * 64;
#pragma unroll
        for (int i = 0; i < 8; i++) {
            int r = lr + 16 * i;
            const __half* asrc;
            if (MODE == 0)
                asrc = g_xh + (size_t)s_tok[r] * DIM + lc * 8 + k0;
            else
                asrc = g_hh + (size_t)(off + min(m0 + r, cnt - 1)) * FFD + lc * 8 + k0;
            cpa16(ab + i * 2048, asrc);
            cpa16(ab + 16384 + i * 2048, bBase + (size_t)i * 16 * KD + k0);
        }
        asm volatile("cp.async.commit_group;" ::: "memory");
    };

    int warp = tid >> 5, lane = tid & 31;
    int g = lane >> 2, tg = lane & 3;
    int wm = (warp & 1) * 64, wn = (warp >> 1) * 64;
    int sub = lane >> 3, rin = lane & 7;
    int arow[4], brow[4];
#pragma unroll
    for (int mi = 0; mi < 4; mi++) arow[mi] = wm + mi * 16 + ((sub & 1) << 3) + rin;
#pragma unroll
    for (int bj = 0; bj < 4; bj++) brow[bj] = wn + bj * 16 + ((sub >> 1) << 3) + rin;
    int qA = sub >> 1, qB = sub & 1;

    float c[4][8][4];
#pragma unroll
    for (int mi = 0; mi < 4; mi++)
#pragma unroll
        for (int nj = 0; nj < 8; nj++)
#pragma unroll
            for (int q = 0; q < 4; q++) c[mi][nj][q] = 0.f;

    fill(0); fill(1);

    for (int ki = 0; ki < KT; ki++) {
        asm volatile("cp.async.wait_group %0;" :: "n"(1) : "memory");
        __syncthreads();
        if (ki + 2 < KT) fill(ki + 2);
        else asm volatile("cp.async.commit_group;" ::: "memory");

        unsigned As = sb + (unsigned)(ki % 3) * 32768u;
        unsigned Bs = As + 16384u;
#pragma unroll
        for (int kc = 0; kc < 4; kc++) {
            unsigned a[4][4], b[4][4];
#pragma unroll
            for (int mi = 0; mi < 4; mi++)
                ldsm4(a[mi], As + arow[mi] * 128 + (((kc * 2 + qA) ^ (arow[mi] & 7)) << 4));
#pragma unroll
            for (int bj = 0; bj < 4; bj++)
                ldsm4(b[bj], Bs + brow[bj] * 128 + (((kc * 2 + qB) ^ (brow[bj] & 7)) << 4));
#pragma unroll
            for (int mi = 0; mi < 4; mi++)
#pragma unroll
                for (int nj = 0; nj < 8; nj++) {
                    const unsigned* bb = b[nj >> 1];
                    if (nj & 1) mma_f16(c[mi][nj], a[mi], bb[2], bb[3]);
                    else        mma_f16(c[mi][nj], a[mi], bb[0], bb[1]);
                }
        }
    }

    // epilogue: c[q]: q0=(row g, col 2tg), q1=(g,2tg+1), q2=(g+8,2tg), q3=(g+8,2tg+1)
#pragma unroll
    for (int mi = 0; mi < 4; mi++) {
#pragma unroll
        for (int rr = 0; rr < 2; rr++) {
            int mloc = wm + mi * 16 + g + rr * 8;
            if (m0 + mloc >= cnt) continue;
            if (MODE == 0) {
                __half* hrow = g_hh + (size_t)(off + m0 + mloc) * FFD + n0;
#pragma unroll
                for (int nj = 0; nj < 8; nj++) {
                    int n = wn + nj * 8 + 2 * tg;
                    float v0 = c[mi][nj][rr * 2 + 0] + s_bias[n];
                    float v1 = c[mi][nj][rr * 2 + 1] + s_bias[n + 1];
                    v0 = v0 > 0.f ? v0 : 0.1f * v0;
                    v1 = v1 > 0.f ? v1 : 0.1f * v1;
                    *(__half2*)(hrow + n) = __floats2half2_rn(v0, v1);
                }
            } else {
                int tok = s_tok[mloc];
                float gt = s_gate[mloc];
                float* orow = out + (size_t)tok * DIM + n0;
#pragma unroll
                for (int nj = 0; nj < 8; nj++) {
                    int n = wn + nj * 8 + 2 * tg;
                    red2(orow + n, (c[mi][nj][rr * 2 + 0] + s_bias[n]) * gt,
                                   (c[mi][nj][rr * 2 + 1] + s_bias[n + 1]) * gt);
                }
            }
        }
    }
}

extern "C" void kernel_launch(void* const* d_in, const int* in_sizes, int n_in,
                              void* d_out, int out_size) {
    const float* x  = (const float*)d_in[0];
    const float* wg = (const float*)d_in[1];
    const float* bg = (const float*)d_in[2];
    const float* w1 = (const float*)d_in[3];
    const float* b1 = (const float*)d_in[4];
    const float* w2 = (const float*)d_in[5];
    const float* b2 = (const float*)d_in[6];
    float* out = (float*)d_out;

    const int base = T_TOK * DIM;
    int has_tail = (out_size >= base + 4 * T_TOK) ? 1 : 0;
    int nb_zero = (out_size / 4 + 255) / 256;

    const int SMEM_BYTES = 3 * 32768 + 2048;
    cudaFuncSetAttribute(k_g<0>, cudaFuncAttributeMaxDynamicSharedMemorySize, SMEM_BYTES);
    cudaFuncSetAttribute(k_g<1>, cudaFuncAttributeMaxDynamicSharedMemorySize, SMEM_BYTES);

    k_init<<<1, 32>>>();
    k_prep<<<NB_W1 + NB_W2 + NB_X + nb_zero + NB_GATE, 256>>>(
        x, wg, bg, w1, w2, out, out_size, has_tail, nb_zero);
    k_offsets<<<1, 1>>>();

    k_g<0><<<dim3(FFD / 128, T_TOK / 128, NEXP), 128, SMEM_BYTES>>>(b1, nullptr);
    k_g<1><<<dim3(DIM / 128, T_TOK / 128, NEXP), 128, SMEM_BYTES>>>(b2, out);
}

// round 16
// speedup vs baseline: 1.0488x; 1.0488x over previous
#include <cuda_runtime.h>
#include <cuda_fp16.h>
#include <cstdint>

#define T_TOK 8192
#define DIM   1024
#define FFD   4096
#define NEXP  8

// ---- static device scratch (no allocations) ----
__device__ int    g_count[NEXP];
__device__ int    g_offset[NEXP];
__device__ int    g_tok[NEXP * T_TOK];
__device__ float  g_gate[NEXP * T_TOK];
__device__ __half g_xh[(size_t)T_TOK * DIM];
__device__ __half g_w1h[(size_t)NEXP * FFD * DIM];
__device__ __half g_w2h[(size_t)NEXP * DIM * FFD];
__device__ __half g_hh[(size_t)T_TOK * 2 * FFD];

__device__ __forceinline__ void cpa16(unsigned dst, const void* src) {
    asm volatile("cp.async.cg.shared.global [%0], [%1], 16;" :: "r"(dst), "l"(src) : "memory");
}
__device__ __forceinline__ void ldsm4(unsigned r[4], unsigned addr) {
    asm volatile("ldmatrix.sync.aligned.m8n8.x4.shared.b16 {%0,%1,%2,%3}, [%4];"
                 : "=r"(r[0]), "=r"(r[1]), "=r"(r[2]), "=r"(r[3]) : "r"(addr));
}
__device__ __forceinline__ void mma_f16(float c[4], const unsigned a[4], unsigned b0, unsigned b1) {
    asm volatile(
        "mma.sync.aligned.m16n8k16.row.col.f32.f16.f16.f32 "
        "{%0,%1,%2,%3}, {%4,%5,%6,%7}, {%8,%9}, {%0,%1,%2,%3};"
        : "+f"(c[0]), "+f"(c[1]), "+f"(c[2]), "+f"(c[3])
        : "r"(a[0]), "r"(a[1]), "r"(a[2]), "r"(a[3]), "r"(b0), "r"(b1));
}
__device__ __forceinline__ void red2(float* p, float v0, float v1) {
    asm volatile("red.global.add.v2.f32 [%0], {%1, %2};" :: "l"(p), "f"(v0), "f"(v1) : "memory");
}

// ---- init routing counters ----
__global__ void k_init() {
    if (threadIdx.x < NEXP) g_count[threadIdx.x] = 0;
}

// block ranges inside k_prep
#define NB_W1   16384
#define NB_W2   16384
#define NB_X    4096
#define NB_GATE 1024

__device__ __forceinline__ void cvt8(const float4* in, uint4* out, int i) {
    float4 a = in[2 * i], b = in[2 * i + 1];
    __half2 h0 = __floats2half2_rn(a.x, a.y);
    __half2 h1 = __floats2half2_rn(a.z, a.w);
    __half2 h2 = __floats2half2_rn(b.x, b.y);
    __half2 h3 = __floats2half2_rn(b.z, b.w);
    uint4 v;
    v.x = *reinterpret_cast<unsigned*>(&h0);
    v.y = *reinterpret_cast<unsigned*>(&h1);
    v.z = *reinterpret_cast<unsigned*>(&h2);
    v.w = *reinterpret_cast<unsigned*>(&h3);
    out[i] = v;
}

// ---- fused prep: weight/x fp16 conversion + out zero + gating, one launch ----
__global__ void __launch_bounds__(256)
k_prep(const float* __restrict__ x, const float* __restrict__ wg,
       const float* __restrict__ bg, const float* __restrict__ w1,
       const float* __restrict__ w2, float* __restrict__ out,
       int out_size, int has_tail, int nb_zero) {
    __shared__ float s_wg[NEXP * DIM];
    __shared__ float s_bg[NEXP];
    int b = blockIdx.x, tid = threadIdx.x;

    if (b < NB_W1) {
        cvt8((const float4*)w1, (uint4*)g_w1h, b * 256 + tid);
        return;
    }
    b -= NB_W1;
    if (b < NB_W2) {
        cvt8((const float4*)w2, (uint4*)g_w2h, b * 256 + tid);
        return;
    }
    b -= NB_W2;
    if (b < NB_X) {
        cvt8((const float4*)x, (uint4*)g_xh, b * 256 + tid);
        return;
    }
    b -= NB_X;
    if (b < nb_zero) {
        int i4 = b * 256 + tid;
        int i = i4 * 4;
        if (i < out_size) {
            const int base = T_TOK * DIM;
            if (!(has_tail && i >= base && i < base + 4 * T_TOK))
                *(float4*)(out + i) = make_float4(0.f, 0.f, 0.f, 0.f);
        }
        return;
    }
    b -= nb_zero;

    // ---- gating: one warp per token, 8 tokens per block ----
    for (int i = tid; i < NEXP * DIM; i += 256) s_wg[i] = wg[i];
    if (tid < NEXP) s_bg[tid] = bg[tid];
    __syncthreads();

    int warp = tid >> 5, lane = tid & 31;
    int t = b * 8 + warp;
    const float* xr = x + (size_t)t * DIM;

    float acc[NEXP];
#pragma unroll
    for (int e = 0; e < NEXP; e++) acc[e] = 0.f;
    for (int d = lane; d < DIM; d += 32) {
        float xv = xr[d];
#pragma unroll
        for (int e = 0; e < NEXP; e++) acc[e] += xv * s_wg[e * DIM + d];
    }
#pragma unroll
    for (int e = 0; e < NEXP; e++) {
#pragma unroll
        for (int o = 16; o > 0; o >>= 1) acc[e] += __shfl_xor_sync(0xffffffffu, acc[e], o);
    }

    if (lane == 0) {
        float p[NEXP];
        float m = -1e30f;
#pragma unroll
        for (int e = 0; e < NEXP; e++) { p[e] = acc[e] + s_bg[e]; m = fmaxf(m, p[e]); }
        float s = 0.f;
#pragma unroll
        for (int e = 0; e < NEXP; e++) { p[e] = expf(p[e] - m); s += p[e]; }
        float inv = 1.f / s;
#pragma unroll
        for (int e = 0; e < NEXP; e++) p[e] *= inv;

        int e1 = 0;
#pragma unroll
        for (int e = 1; e < NEXP; e++) if (p[e] > p[e1]) e1 = e;
        int e2 = (e1 == 0) ? 1 : 0;
#pragma unroll
        for (int e = 0; e < NEXP; e++) if (e != e1 && p[e] > p[e2]) e2 = e;

        int pos1 = atomicAdd(&g_count[e1], 1);
        g_tok[e1 * T_TOK + pos1]  = t;
        g_gate[e1 * T_TOK + pos1] = p[e1];
        int pos2 = atomicAdd(&g_count[e2], 1);
        g_tok[e2 * T_TOK + pos2]  = t;
        g_gate[e2 * T_TOK + pos2] = p[e2];

        if (has_tail) {
            float* tail = out + (size_t)T_TOK * DIM;
            tail[t * 2 + 0] = (float)e1;
            tail[t * 2 + 1] = (float)e2;
            tail[T_TOK * 2 + t * 2 + 0] = p[e1];
            tail[T_TOK * 2 + t * 2 + 1] = p[e2];
        }
    }
}

__global__ void k_offsets() {
    int s = 0;
    for (int e = 0; e < NEXP; e++) { g_offset[e] = s; s += g_count[e]; }
}

// ==== GEMM0: x @ w1^T -> h.  128x128 CTA tile, 4 warps x 64x64 warp tile, ====
// 128 threads, BK=64, 3-stage cp.async, fragment double-buffer across kc.
__global__ void __launch_bounds__(128, 2)
k_g0(const float* __restrict__ bias) {
    constexpr int KD = DIM, KT = KD / 64;

    int e = blockIdx.z;
    int cnt = g_count[e];
    int m0 = blockIdx.y * 128;
    if (m0 >= cnt) return;
    int n0 = blockIdx.x * 128;
    int off = g_offset[e];

    extern __shared__ __align__(1024) char sm[];
    const unsigned sb = (unsigned)__cvta_generic_to_shared(sm);
    int*   s_tok  = (int*)(sm + 98304);
    float* s_bias = (float*)(sm + 98304 + 1024);

    int tid = threadIdx.x;
    {
        int mc = min(m0 + tid, cnt - 1);
        s_tok[tid]  = g_tok[e * T_TOK + mc];
        s_bias[tid] = bias[(size_t)e * FFD + n0 + tid];
    }
    __syncthreads();

    const __half* Wb = g_w1h + (size_t)e * FFD * KD;

    int lr = tid >> 3, lc = tid & 7;
    const unsigned soff = (unsigned)(lr * 128 + ((lc ^ (lr & 7)) << 4));
    const __half* bBase = Wb + (size_t)(n0 + lr) * KD + lc * 8;

    auto fill = [&](int j) {
        unsigned ab = sb + (unsigned)(j % 3) * 32768u + soff;
        const int k0 = j * 64;
#pragma unroll
        for (int i = 0; i < 8; i++) {
            int r = lr + 16 * i;
            cpa16(ab + i * 2048, g_xh + (size_t)s_tok[r] * DIM + lc * 8 + k0);
            cpa16(ab + 16384 + i * 2048, bBase + (size_t)i * 16 * KD + k0);
        }
        asm volatile("cp.async.commit_group;" ::: "memory");
    };

    int warp = tid >> 5, lane = tid & 31;
    int g = lane >> 2, tg = lane & 3;
    int wm = (warp & 1) * 64, wn = (warp >> 1) * 64;
    int sub = lane >> 3, rin = lane & 7;
    int arow[4], brow[4];
#pragma unroll
    for (int mi = 0; mi < 4; mi++) arow[mi] = wm + mi * 16 + ((sub & 1) << 3) + rin;
#pragma unroll
    for (int bj = 0; bj < 4; bj++) brow[bj] = wn + bj * 16 + ((sub >> 1) << 3) + rin;
    int qA = sub >> 1, qB = sub & 1;

    float c[4][8][4];
#pragma unroll
    for (int mi = 0; mi < 4; mi++)
#pragma unroll
        for (int nj = 0; nj < 8; nj++)
#pragma unroll
            for (int q = 0; q < 4; q++) c[mi][nj][q] = 0.f;

    fill(0); fill(1);

    unsigned aF[2][4][4], bF[2][4][4];

    auto loadfrag = [&](unsigned As, unsigned Bs, int kc, int buf) {
#pragma unroll
        for (int mi = 0; mi < 4; mi++)
            ldsm4(aF[buf][mi], As + arow[mi] * 128 + (((kc * 2 + qA) ^ (arow[mi] & 7)) << 4));
#pragma unroll
        for (int bj = 0; bj < 4; bj++)
            ldsm4(bF[buf][bj], Bs + brow[bj] * 128 + (((kc * 2 + qB) ^ (brow[bj] & 7)) << 4));
    };
    auto compute = [&](int buf) {
#pragma unroll
        for (int mi = 0; mi < 4; mi++)
#pragma unroll
            for (int nj = 0; nj < 8; nj++) {
                const unsigned* bb = bF[buf][nj >> 1];
                if (nj & 1) mma_f16(c[mi][nj], aF[buf][mi], bb[2], bb[3]);
                else        mma_f16(c[mi][nj], aF[buf][mi], bb[0], bb[1]);
            }
    };

    for (int ki = 0; ki < KT; ki++) {
        asm volatile("cp.async.wait_group %0;" :: "n"(1) : "memory");
        __syncthreads();
        if (ki + 2 < KT) fill(ki + 2);
        else asm volatile("cp.async.commit_group;" ::: "memory");

        unsigned As = sb + (unsigned)(ki % 3) * 32768u;
        unsigned Bs = As + 16384u;
        loadfrag(As, Bs, 0, 0);
#pragma unroll
        for (int kc = 0; kc < 4; kc++) {
            if (kc < 3) loadfrag(As, Bs, kc + 1, (kc + 1) & 1);
            compute(kc & 1);
        }
    }

    // epilogue -> h (fp16, leaky + bias)
#pragma unroll
    for (int mi = 0; mi < 4; mi++) {
#pragma unroll
        for (int rr = 0; rr < 2; rr++) {
            int mloc = wm + mi * 16 + g + rr * 8;
            if (m0 + mloc >= cnt) continue;
            __half* hrow = g_hh + (size_t)(off + m0 + mloc) * FFD + n0;
#pragma unroll
            for (int nj = 0; nj < 8; nj++) {
                int n = wn + nj * 8 + 2 * tg;
                float v0 = c[mi][nj][rr * 2 + 0] + s_bias[n];
                float v1 = c[mi][nj][rr * 2 + 1] + s_bias[n + 1];
                v0 = v0 > 0.f ? v0 : 0.1f * v0;
                v1 = v1 > 0.f ? v1 : 0.1f * v1;
                *(__half2*)(hrow + n) = __floats2half2_rn(v0, v1);
            }
        }
    }
}

// ==== GEMM1: h @ w2^T -> out.  128x128 CTA tile, 8 warps x 32x64 warp tile ====
// (proven R14 shape: 256 threads, BK=64, 3-stage)
__global__ void __launch_bounds__(256, 2)
k_g1(const float* __restrict__ bias, float* __restrict__ out) {
    constexpr int KD = FFD, KT = KD / 64;

    int e = blockIdx.z;
    int cnt = g_count[e];
    int m0 = blockIdx.y * 128;
    if (m0 >= cnt) return;
    int n0 = blockIdx.x * 128;
    int off = g_offset[e];

    extern __shared__ __align__(1024) char sm[];
    const unsigned sb = (unsigned)__cvta_generic_to_shared(sm);
    int*   s_tok  = (int*)(sm + 98304);
    float* s_gate = (float*)(sm + 98304 + 512);
    float* s_bias = (float*)(sm + 98304 + 1024);

    int tid = threadIdx.x;
    if (tid < 128) {
        int mc = min(m0 + tid, cnt - 1);
        s_tok[tid]  = g_tok[e * T_TOK + mc];
        s_gate[tid] = g_gate[e * T_TOK + mc];
        s_bias[tid] = bias[(size_t)e * DIM + n0 + tid];
    }
    __syncthreads();

    const __half* Wb = g_w2h + (size_t)e * DIM * KD;

    int lr = tid >> 3, lc = tid & 7;
    const __half* aP[4];
    const __half* bP[4];
#pragma unroll
    for (int i = 0; i < 4; i++) {
        int r = lr + 32 * i;
        aP[i] = g_hh + (size_t)(off + min(m0 + r, cnt - 1)) * FFD + lc * 8;
        bP[i] = Wb + (size_t)(n0 + r) * KD + lc * 8;
    }
    const unsigned soff = (unsigned)(lr * 128 + ((lc ^ (lr & 7)) << 4));

    auto fill = [&](int j) {
        unsigned ab = sb + (unsigned)(j % 3) * 32768u + soff;
        const int k0 = j * 64;
#pragma unroll
        for (int i = 0; i < 4; i++) {
            cpa16(ab + i * 4096, aP[i] + k0);
            cpa16(ab + 16384 + i * 4096, bP[i] + k0);
        }
        asm volatile("cp.async.commit_group;" ::: "memory");
    };

    int warp = tid >> 5, lane = tid & 31;
    int g = lane >> 2, tg = lane & 3;
    int wm = (warp & 3) * 32, wn = (warp >> 2) * 64;
    int sub = lane >> 3, rin = lane & 7;
    int arow[2], brow[4];
#pragma unroll
    for (int mi = 0; mi < 2; mi++) arow[mi] = wm + mi * 16 + ((sub & 1) << 3) + rin;
#pragma unroll
    for (int bj = 0; bj < 4; bj++) brow[bj] = wn + bj * 16 + ((sub >> 1) << 3) + rin;
    int qA = sub >> 1, qB = sub & 1;

    float c[2][8][4];
#pragma unroll
    for (int mi = 0; mi < 2; mi++)
#pragma unroll
        for (int nj = 0; nj < 8; nj++)
#pragma unroll
            for (int q = 0; q < 4; q++) c[mi][nj][q] = 0.f;

    fill(0); fill(1);

    for (int ki = 0; ki < KT; ki++) {
        asm volatile("cp.async.wait_group %0;" :: "n"(1) : "memory");
        __syncthreads();
        if (ki + 2 < KT) fill(ki + 2);
        else asm volatile("cp.async.commit_group;" ::: "memory");

        unsigned As = sb + (unsigned)(ki % 3) * 32768u;
        unsigned Bs = As + 16384u;
#pragma unroll
        for (int kc = 0; kc < 4; kc++) {
            unsigned a[2][4], b[4][4];
#pragma unroll
            for (int mi = 0; mi < 2; mi++)
                ldsm4(a[mi], As + arow[mi] * 128 + (((kc * 2 + qA) ^ (arow[mi] & 7)) << 4));
#pragma unroll
            for (int bj = 0; bj < 4; bj++)
                ldsm4(b[bj], Bs + brow[bj] * 128 + (((kc * 2 + qB) ^ (brow[bj] & 7)) << 4));
#pragma unroll
            for (int mi = 0; mi < 2; mi++)
#pragma unroll
                for (int nj = 0; nj < 8; nj++) {
                    const unsigned* bb = b[nj >> 1];
                    if (nj & 1) mma_f16(c[mi][nj], a[mi], bb[2], bb[3]);
                    else        mma_f16(c[mi][nj], a[mi], bb[0], bb[1]);
                }
        }
    }

    // epilogue -> red.v2 scatter
#pragma unroll
    for (int mi = 0; mi < 2; mi++) {
#pragma unroll
        for (int rr = 0; rr < 2; rr++) {
            int mloc = wm + mi * 16 + g + rr * 8;
            if (m0 + mloc >= cnt) continue;
            int tok = s_tok[mloc];
            float gt = s_gate[mloc];
            float* orow = out + (size_t)tok * DIM + n0;
#pragma unroll
            for (int nj = 0; nj < 8; nj++) {
                int n = wn + nj * 8 + 2 * tg;
                red2(orow + n, (c[mi][nj][rr * 2 + 0] + s_bias[n]) * gt,
                               (c[mi][nj][rr * 2 + 1] + s_bias[n + 1]) * gt);
            }
        }
    }
}

extern "C" void kernel_launch(void* const* d_in, const int* in_sizes, int n_in,
                              void* d_out, int out_size) {
    const float* x  = (const float*)d_in[0];
    const float* wg = (const float*)d_in[1];
    const float* bg = (const float*)d_in[2];
    const float* w1 = (const float*)d_in[3];
    const float* b1 = (const float*)d_in[4];
    const float* w2 = (const float*)d_in[5];
    const float* b2 = (const float*)d_in[6];
    float* out = (float*)d_out;

    const int base = T_TOK * DIM;
    int has_tail = (out_size >= base + 4 * T_TOK) ? 1 : 0;
    int nb_zero = (out_size / 4 + 255) / 256;

    const int SMEM_BYTES = 3 * 32768 + 2048;
    cudaFuncSetAttribute(k_g0, cudaFuncAttributeMaxDynamicSharedMemorySize, SMEM_BYTES);
    cudaFuncSetAttribute(k_g1, cudaFuncAttributeMaxDynamicSharedMemorySize, SMEM_BYTES);

    k_init<<<1, 32>>>();
    k_prep<<<NB_W1 + NB_W2 + NB_X + nb_zero + NB_GATE, 256>>>(
        x, wg, bg, w1, w2, out, out_size, has_tail, nb_zero);
    k_offsets<<<1, 1>>>();

    k_g0<<<dim3(FFD / 128, T_TOK / 128, NEXP), 128, SMEM_BYTES>>>(b1);
    k_g1<<<dim3(DIM / 128, T_TOK / 128, NEXP), 256, SMEM_BYTES>>>(b2, out);
}